// round 1
// baseline (speedup 1.0000x reference)
#include <cuda_runtime.h>
#include <cstdint>

#define N_NODES 100000
#define E_EDGES 3200000
#define F_INDIM 512
#define F_OUTDIM 256
#define ALPHA   0.2f
#define EPSV    9e-15f

// ---------------- scratch (static device globals; no allocation) ----------------
__device__ float    g_h[(size_t)N_NODES * F_OUTDIM];   // 102.4 MB
__device__ float    g_el[N_NODES];
__device__ float    g_er[N_NODES];
__device__ float    g_rowsum[N_NODES];
__device__ unsigned g_max_enc;
__device__ int      g_is64;

// ordered-float encoding for atomicMax
__device__ __forceinline__ unsigned fenc(float f) {
    unsigned u = __float_as_uint(f);
    return (u & 0x80000000u) ? ~u : (u | 0x80000000u);
}
__device__ __forceinline__ float fdec(unsigned u) {
    return __uint_as_float((u & 0x80000000u) ? (u & 0x7fffffffu) : ~u);
}

// edge accessor: e32 points at raw edge buffer; if is64, entries are int64
// (little-endian: low word at 2*idx), values < 2^31 so low word suffices.
__device__ __forceinline__ int edge_at(const int* __restrict__ e32, int is64, long long idx) {
    return is64 ? e32[2 * idx] : e32[(size_t)idx];
}

__device__ __forceinline__ void red_add_v4(float* addr, float a, float b, float c, float d) {
    asm volatile("red.global.add.v4.f32 [%0], {%1,%2,%3,%4};"
                 :: "l"(addr), "f"(a), "f"(b), "f"(c), "f"(d) : "memory");
}

// ---------------- init: zero accumulators, reset max, detect edge dtype ----------------
__global__ void k_init(float* __restrict__ out, const int* __restrict__ edge_raw) {
    size_t tid = (size_t)blockIdx.x * blockDim.x + threadIdx.x;
    size_t stride = (size_t)gridDim.x * blockDim.x;
    size_t total = (size_t)N_NODES * F_OUTDIM;
    for (size_t i = tid; i < total; i += stride) out[i] = 0.0f;
    for (size_t i = tid; i < N_NODES; i += stride) g_rowsum[i] = 0.0f;
    if (tid == 0) {
        g_max_enc = 0u;  // below enc(-inf)
        // int64 detection: odd words of first 16 entries all zero
        int all_zero = 1;
        for (int k = 0; k < 16; k++) all_zero &= (edge_raw[2 * k + 1] == 0);
        g_is64 = all_zero;
    }
}

// ---------------- SGEMM: h = x @ W + bias  (M=100000, K=512, Ncols=256) ----------------
// 128x128 tile, BK=8, 256 threads, 8x8 micro-tile per thread.
__global__ void __launch_bounds__(256) k_gemm(const float* __restrict__ A,
                                              const float* __restrict__ W,
                                              const float* __restrict__ bias) {
    __shared__ float As[8][128];
    __shared__ float Bs[8][128];
    const int tid = threadIdx.x;
    const int rowBlk = blockIdx.y * 128;
    const int colBlk = blockIdx.x * 128;
    const int ty = tid >> 4;         // 0..15
    const int tx = tid & 15;         // 0..15

    float acc[8][8];
    #pragma unroll
    for (int i = 0; i < 8; i++)
        #pragma unroll
        for (int j = 0; j < 8; j++) acc[i][j] = 0.0f;

    const int arow = tid >> 1;           // 0..127
    const int ak   = (tid & 1) << 2;     // 0 or 4
    const int brow = tid >> 5;           // 0..7
    const int bcol = (tid & 31) << 2;    // 0..124

    const bool avalid = (rowBlk + arow) < N_NODES;
    const float* Aptr = A + (size_t)(rowBlk + arow) * F_INDIM + ak;
    const float* Bptr = W + (size_t)brow * F_OUTDIM + colBlk + bcol;

    for (int kt = 0; kt < F_INDIM; kt += 8) {
        float4 av = avalid ? *(const float4*)(Aptr + kt) : make_float4(0.f, 0.f, 0.f, 0.f);
        float4 bv = *(const float4*)(Bptr + (size_t)kt * F_OUTDIM);
        As[ak + 0][arow] = av.x;
        As[ak + 1][arow] = av.y;
        As[ak + 2][arow] = av.z;
        As[ak + 3][arow] = av.w;
        *(float4*)&Bs[brow][bcol] = bv;
        __syncthreads();

        #pragma unroll
        for (int k = 0; k < 8; k++) {
            float ra[8], rb[8];
            #pragma unroll
            for (int i = 0; i < 8; i++) ra[i] = As[k][ty * 8 + i];
            #pragma unroll
            for (int j = 0; j < 8; j++) rb[j] = Bs[k][tx * 8 + j];
            #pragma unroll
            for (int i = 0; i < 8; i++)
                #pragma unroll
                for (int j = 0; j < 8; j++) acc[i][j] += ra[i] * rb[j];
        }
        __syncthreads();
    }

    #pragma unroll
    for (int i = 0; i < 8; i++) {
        int r = rowBlk + ty * 8 + i;
        if (r < N_NODES) {
            float* hrow = g_h + (size_t)r * F_OUTDIM + colBlk + tx * 8;
            #pragma unroll
            for (int j = 0; j < 8; j++)
                hrow[j] = acc[i][j] + bias[colBlk + tx * 8 + j];
        }
    }
}

// ---------------- per-node attention dots: el = h.a_src, er = h.a_dst ----------------
__global__ void __launch_bounds__(256) k_dots(const float* __restrict__ avec) {
    int gw   = (blockIdx.x * 256 + threadIdx.x) >> 5;
    int lane = threadIdx.x & 31;
    if (gw >= N_NODES) return;
    const float4* h4 = (const float4*)(g_h + (size_t)gw * F_OUTDIM);
    const float4* a1 = (const float4*)avec;
    const float4* a2 = (const float4*)(avec + F_OUTDIM);
    float s1 = 0.f, s2 = 0.f;
    #pragma unroll
    for (int i = 0; i < 2; i++) {
        int idx = lane + i * 32;
        float4 h = h4[idx];
        float4 x1 = a1[idx];
        float4 x2 = a2[idx];
        s1 += h.x * x1.x + h.y * x1.y + h.z * x1.z + h.w * x1.w;
        s2 += h.x * x2.x + h.y * x2.y + h.z * x2.z + h.w * x2.w;
    }
    #pragma unroll
    for (int o = 16; o; o >>= 1) {
        s1 += __shfl_xor_sync(0xffffffffu, s1, o);
        s2 += __shfl_xor_sync(0xffffffffu, s2, o);
    }
    if (lane == 0) { g_el[gw] = s1; g_er[gw] = s2; }
}

// ---------------- global max over leaky-relu'd edge scores ----------------
__global__ void __launch_bounds__(256) k_edge_max(const int* __restrict__ edge_raw) {
    const int is64 = g_is64;
    float m = -3.402823466e38f;
    int stride = gridDim.x * blockDim.x;
    for (int i = blockIdx.x * blockDim.x + threadIdx.x; i < E_EDGES; i += stride) {
        int s = edge_at(edge_raw, is64, i);
        int d = edge_at(edge_raw, is64, (long long)E_EDGES + i);
        float e = g_el[s] + g_er[d];
        e = e > 0.f ? e : ALPHA * e;
        m = fmaxf(m, e);
    }
    #pragma unroll
    for (int o = 16; o; o >>= 1) m = fmaxf(m, __shfl_xor_sync(0xffffffffu, m, o));
    __shared__ float sm[8];
    int lane = threadIdx.x & 31, w = threadIdx.x >> 5;
    if (lane == 0) sm[w] = m;
    __syncthreads();
    if (threadIdx.x == 0) {
        float bm = sm[0];
        #pragma unroll
        for (int i = 1; i < 8; i++) bm = fmaxf(bm, sm[i]);
        atomicMax(&g_max_enc, fenc(bm));
    }
}

// ---------------- edge scatter: out[src] += w * h[dst]; rowsum[src] += w ----------------
// one warp per edge; 32 lanes x 8 floats; vectorized red.global.add.v4.f32
__global__ void __launch_bounds__(256) k_scatter(const int* __restrict__ edge_raw,
                                                 float* __restrict__ out) {
    const int is64 = g_is64;
    const float gmax = fdec(g_max_enc);
    int lane = threadIdx.x & 31;
    int gw = (blockIdx.x * 256 + threadIdx.x) >> 5;
    int nwarps = (gridDim.x * 256) >> 5;
    for (int e = gw; e < E_EDGES; e += nwarps) {
        int s = edge_at(edge_raw, is64, e);
        int d = edge_at(edge_raw, is64, (long long)E_EDGES + e);
        float ev = g_el[s] + g_er[d];
        ev = ev > 0.f ? ev : ALPHA * ev;
        float w = expf(ev - gmax);
        const float4* h4 = (const float4*)(g_h + (size_t)d * F_OUTDIM);
        float* orow = out + (size_t)s * F_OUTDIM;
        #pragma unroll
        for (int i = 0; i < 2; i++) {
            int idx = lane + i * 32;
            float4 h = h4[idx];
            red_add_v4(orow + idx * 4, h.x * w, h.y * w, h.z * w, h.w * w);
        }
        if (lane == 0) atomicAdd(&g_rowsum[s], w);
    }
}

// ---------------- finalize: out = elu(out / (rowsum + EPS)) ----------------
__global__ void k_final(float* __restrict__ out) {
    size_t idx = (size_t)blockIdx.x * blockDim.x + threadIdx.x;
    size_t stride = (size_t)gridDim.x * blockDim.x;
    size_t total = (size_t)N_NODES * F_OUTDIM;
    for (; idx < total; idx += stride) {
        float rs = g_rowsum[idx >> 8];   // F_OUTDIM = 256
        float v = out[idx] / (rs + EPSV);
        out[idx] = v > 0.f ? v : expm1f(v);
    }
}

// ---------------- launch ----------------
extern "C" void kernel_launch(void* const* d_in, const int* in_sizes, int n_in,
                              void* d_out, int out_size) {
    const float* x    = (const float*)d_in[0];
    const int*   edge = (const int*)d_in[1];   // int32 or int64, auto-detected
    const float* W    = (const float*)d_in[2];
    const float* a    = (const float*)d_in[3];
    const float* bias = (const float*)d_in[4];
    float* out = (float*)d_out;

    k_init<<<1024, 256>>>(out, edge);

    dim3 ggrid(2, (N_NODES + 127) / 128);
    k_gemm<<<ggrid, 256>>>(x, W, bias);

    k_dots<<<(N_NODES + 7) / 8, 256>>>(a);
    k_edge_max<<<1024, 256>>>(edge);
    k_scatter<<<4096, 256>>>(edge, out);
    k_final<<<1024, 256>>>(out);
}

// round 5
// speedup vs baseline: 2.5238x; 2.5238x over previous
#include <cuda_runtime.h>
#include <cstdint>

#define N_NODES 100000
#define E_EDGES 3200000
#define F_INDIM 512
#define F_OUTDIM 256
#define ALPHA   0.2f
#define EPSV    9e-15f

#define SCAN_BS 512
#define SCAN_NB 196   // 196*512 = 100352 >= 100000

// ---------------- scratch (static device globals; no allocation) ----------------
__device__ __align__(16) float g_h[(size_t)N_NODES * F_OUTDIM];   // 102.4 MB
__device__ float    g_el[N_NODES];
__device__ float    g_er[N_NODES];
__device__ int      g_deg[N_NODES];
__device__ int      g_cursor[N_NODES];
__device__ int      g_rowptr[N_NODES];
__device__ int      g_scan[SCAN_NB * SCAN_BS];
__device__ int      g_bsum[SCAN_NB];
__device__ int      g_boff[SCAN_NB];
__device__ int      g_dstl[E_EDGES];    // CSR neighbor lists
__device__ float    g_wl[E_EDGES];
__device__ unsigned g_max_enc;
__device__ int      g_is64;

// ---------------- helpers ----------------
__device__ __forceinline__ unsigned fenc(float f) {
    unsigned u = __float_as_uint(f);
    return (u & 0x80000000u) ? ~u : (u | 0x80000000u);
}
__device__ __forceinline__ float fdec(unsigned u) {
    return __uint_as_float((u & 0x80000000u) ? (u & 0x7fffffffu) : ~u);
}
__device__ __forceinline__ int edge_at(const int* __restrict__ e32, int is64, long long idx) {
    return is64 ? e32[2 * idx] : e32[(size_t)idx];
}
__device__ __forceinline__ float totf32(float x) {
    uint32_t r;
    asm("cvt.rna.tf32.f32 %0, %1;" : "=r"(r) : "f"(x));
    return __uint_as_float(r);
}

// ---------------- init: zero deg/cursor, reset max, detect edge dtype ----------------
__global__ void k_init(const int* __restrict__ edge_raw) {
    int i = blockIdx.x * blockDim.x + threadIdx.x;
    int stride = gridDim.x * blockDim.x;
    for (; i < N_NODES; i += stride) { g_deg[i] = 0; g_cursor[i] = 0; }
    if (blockIdx.x == 0 && threadIdx.x == 0) {
        g_max_enc = 0u;
        int all_zero = 1;
        for (int k = 0; k < 16; k++) all_zero &= (edge_raw[2 * k + 1] == 0);
        g_is64 = all_zero;
    }
}

// ---------------- GEMM: h = x @ W + bias  via mma.sync m16n8k8 tf32 ----------------
// CTA 256 thr (8 warps as 4Mx2N), tile 128x128, KC=32.
// As[m][k] stride 36 (frag-load banks 4g+t: bijective); Bs[k][n] stride 136 (banks 8t+g).
#define KC 32
#define AS_STR 36
#define BS_STR 136

__global__ void __launch_bounds__(256) k_gemm(const float* __restrict__ x,
                                              const float* __restrict__ W,
                                              const float* __restrict__ bias) {
    __shared__ float As[128 * AS_STR];
    __shared__ float Bs[KC * BS_STR];
    __shared__ float sbias[128];

    const int tid = threadIdx.x;
    const int wid = tid >> 5, lane = tid & 31;
    const int g = lane >> 2, tg = lane & 3;
    const int warpM = wid >> 1, warpN = wid & 1;
    const int rowBlk = blockIdx.y * 128;
    const int colBlk = blockIdx.x * 128;

    if (tid < 128) sbias[tid] = bias[colBlk + tid];

    float acc[2][8][4];
    #pragma unroll
    for (int mt = 0; mt < 2; mt++)
        #pragma unroll
        for (int nt = 0; nt < 8; nt++)
            #pragma unroll
            for (int r = 0; r < 4; r++) acc[mt][nt][r] = 0.0f;

    // gmem staging addressing
    const int am  = tid >> 1;              // 0..127
    const int ak0 = (tid & 1) * 16;        // 0 / 16
    const int br  = tid >> 3;              // 0..31
    const int bc0 = (tid & 7) * 16;        // 0..112
    const bool avalid = (rowBlk + am) < N_NODES;
    const float* aptr = x + (size_t)(rowBlk + am) * F_INDIM + ak0;
    const float* bptr = W + (size_t)br * F_OUTDIM + colBlk + bc0;

    float4 ra[4], rb[4];

    // load chunk 0
    #pragma unroll
    for (int j = 0; j < 4; j++) {
        ra[j] = avalid ? ((const float4*)(aptr))[j] : make_float4(0.f, 0.f, 0.f, 0.f);
        rb[j] = ((const float4*)(bptr))[j];
    }
    #pragma unroll
    for (int j = 0; j < 4; j++) {
        float4 t = ra[j];
        t.x = totf32(t.x); t.y = totf32(t.y); t.z = totf32(t.z); t.w = totf32(t.w);
        *(float4*)&As[am * AS_STR + ak0 + j * 4] = t;
        float4 u = rb[j];
        u.x = totf32(u.x); u.y = totf32(u.y); u.z = totf32(u.z); u.w = totf32(u.w);
        *(float4*)&Bs[br * BS_STR + bc0 + j * 4] = u;
    }
    __syncthreads();

    for (int c = 0; c < F_INDIM / KC; c++) {
        // prefetch next chunk into regs (overlaps with compute)
        if (c < F_INDIM / KC - 1) {
            int kt = (c + 1) * KC;
            #pragma unroll
            for (int j = 0; j < 4; j++) {
                ra[j] = avalid ? ((const float4*)(aptr + kt))[j] : make_float4(0.f, 0.f, 0.f, 0.f);
                rb[j] = ((const float4*)(bptr + (size_t)kt * F_OUTDIM))[j];
            }
        }
        // compute current chunk
        #pragma unroll
        for (int kk = 0; kk < KC; kk += 8) {
            uint32_t af[2][4];
            #pragma unroll
            for (int mt = 0; mt < 2; mt++) {
                int m0 = warpM * 32 + mt * 16;
                af[mt][0] = __float_as_uint(As[(m0 + g) * AS_STR + kk + tg]);
                af[mt][1] = __float_as_uint(As[(m0 + g + 8) * AS_STR + kk + tg]);
                af[mt][2] = __float_as_uint(As[(m0 + g) * AS_STR + kk + tg + 4]);
                af[mt][3] = __float_as_uint(As[(m0 + g + 8) * AS_STR + kk + tg + 4]);
            }
            uint32_t bf[8][2];
            #pragma unroll
            for (int nt = 0; nt < 8; nt++) {
                int n0 = warpN * 64 + nt * 8 + g;
                bf[nt][0] = __float_as_uint(Bs[(kk + tg) * BS_STR + n0]);
                bf[nt][1] = __float_as_uint(Bs[(kk + tg + 4) * BS_STR + n0]);
            }
            #pragma unroll
            for (int mt = 0; mt < 2; mt++)
                #pragma unroll
                for (int nt = 0; nt < 8; nt++) {
                    asm volatile(
                        "mma.sync.aligned.m16n8k8.row.col.f32.tf32.tf32.f32 "
                        "{%0,%1,%2,%3}, {%4,%5,%6,%7}, {%8,%9}, {%0,%1,%2,%3};"
                        : "+f"(acc[mt][nt][0]), "+f"(acc[mt][nt][1]),
                          "+f"(acc[mt][nt][2]), "+f"(acc[mt][nt][3])
                        : "r"(af[mt][0]), "r"(af[mt][1]), "r"(af[mt][2]), "r"(af[mt][3]),
                          "r"(bf[nt][0]), "r"(bf[nt][1]));
                }
        }
        __syncthreads();
        if (c < F_INDIM / KC - 1) {
            #pragma unroll
            for (int j = 0; j < 4; j++) {
                float4 t = ra[j];
                t.x = totf32(t.x); t.y = totf32(t.y); t.z = totf32(t.z); t.w = totf32(t.w);
                *(float4*)&As[am * AS_STR + ak0 + j * 4] = t;
                float4 u = rb[j];
                u.x = totf32(u.x); u.y = totf32(u.y); u.z = totf32(u.z); u.w = totf32(u.w);
                *(float4*)&Bs[br * BS_STR + bc0 + j * 4] = u;
            }
            __syncthreads();
        }
    }

    // epilogue: acc -> g_h with bias
    #pragma unroll
    for (int mt = 0; mt < 2; mt++) {
        #pragma unroll
        for (int rr = 0; rr < 2; rr++) {
            int rloc = warpM * 32 + mt * 16 + g + rr * 8;
            int grow = rowBlk + rloc;
            if (grow < N_NODES) {
                float* hp = g_h + (size_t)grow * F_OUTDIM + colBlk + warpN * 64;
                #pragma unroll
                for (int nt = 0; nt < 8; nt++) {
                    int col = nt * 8 + tg * 2;
                    float2 v;
                    v.x = acc[mt][nt][rr * 2 + 0] + sbias[warpN * 64 + col];
                    v.y = acc[mt][nt][rr * 2 + 1] + sbias[warpN * 64 + col + 1];
                    *(float2*)(hp + col) = v;
                }
            }
        }
    }
}

// ---------------- per-node attention dots ----------------
__global__ void __launch_bounds__(256) k_dots(const float* __restrict__ avec) {
    int gw   = (blockIdx.x * 256 + threadIdx.x) >> 5;
    int lane = threadIdx.x & 31;
    if (gw >= N_NODES) return;
    const float4* h4 = (const float4*)(g_h + (size_t)gw * F_OUTDIM);
    const float4* a1 = (const float4*)avec;
    const float4* a2 = (const float4*)(avec + F_OUTDIM);
    float s1 = 0.f, s2 = 0.f;
    #pragma unroll
    for (int i = 0; i < 2; i++) {
        int idx = lane + i * 32;
        float4 h = h4[idx];
        float4 x1 = a1[idx];
        float4 x2 = a2[idx];
        s1 += h.x * x1.x + h.y * x1.y + h.z * x1.z + h.w * x1.w;
        s2 += h.x * x2.x + h.y * x2.y + h.z * x2.z + h.w * x2.w;
    }
    #pragma unroll
    for (int o = 16; o; o >>= 1) {
        s1 += __shfl_xor_sync(0xffffffffu, s1, o);
        s2 += __shfl_xor_sync(0xffffffffu, s2, o);
    }
    if (lane == 0) { g_el[gw] = s1; g_er[gw] = s2; }
}

// ---------------- CSR build: count, scan (3 passes), fill ----------------
__global__ void __launch_bounds__(256) k_count(const int* __restrict__ edge_raw) {
    const int is64 = g_is64;
    int stride = gridDim.x * blockDim.x;
    for (int i = blockIdx.x * blockDim.x + threadIdx.x; i < E_EDGES; i += stride) {
        int s = edge_at(edge_raw, is64, i);
        atomicAdd(&g_deg[s], 1);
    }
}

__global__ void __launch_bounds__(SCAN_BS) k_scan1() {
    __shared__ int sm[SCAN_BS];
    int t = threadIdx.x;
    int i = blockIdx.x * SCAN_BS + t;
    int v = (i < N_NODES) ? g_deg[i] : 0;
    sm[t] = v;
    __syncthreads();
    #pragma unroll
    for (int off = 1; off < SCAN_BS; off <<= 1) {
        int add = (t >= off) ? sm[t - off] : 0;
        __syncthreads();
        sm[t] += add;
        __syncthreads();
    }
    g_scan[i] = sm[t];
    if (t == SCAN_BS - 1) g_bsum[blockIdx.x] = sm[t];
}

__global__ void k_scan2() {
    __shared__ int sm[SCAN_NB];
    int t = threadIdx.x;
    if (t < SCAN_NB) sm[t] = g_bsum[t];
    __syncthreads();
    if (t == 0) {
        int run = 0;
        for (int i = 0; i < SCAN_NB; i++) { int v = sm[i]; sm[i] = run; run += v; }
    }
    __syncthreads();
    if (t < SCAN_NB) g_boff[t] = sm[t];
}

__global__ void __launch_bounds__(SCAN_BS) k_scan3() {
    int i = blockIdx.x * SCAN_BS + threadIdx.x;
    if (i < N_NODES)
        g_rowptr[i] = g_scan[i] - g_deg[i] + g_boff[blockIdx.x];
}

// ---------------- global max over leaky-relu'd edge scores ----------------
__global__ void __launch_bounds__(256) k_edge_max(const int* __restrict__ edge_raw) {
    const int is64 = g_is64;
    float m = -3.402823466e38f;
    int stride = gridDim.x * blockDim.x;
    for (int i = blockIdx.x * blockDim.x + threadIdx.x; i < E_EDGES; i += stride) {
        int s = edge_at(edge_raw, is64, i);
        int d = edge_at(edge_raw, is64, (long long)E_EDGES + i);
        float e = g_el[s] + g_er[d];
        e = e > 0.f ? e : ALPHA * e;
        m = fmaxf(m, e);
    }
    #pragma unroll
    for (int o = 16; o; o >>= 1) m = fmaxf(m, __shfl_xor_sync(0xffffffffu, m, o));
    __shared__ float sm[8];
    int lane = threadIdx.x & 31, w = threadIdx.x >> 5;
    if (lane == 0) sm[w] = m;
    __syncthreads();
    if (threadIdx.x == 0) {
        float bm = sm[0];
        #pragma unroll
        for (int i = 1; i < 8; i++) bm = fmaxf(bm, sm[i]);
        atomicMax(&g_max_enc, fenc(bm));
    }
}

// ---------------- fill CSR lists with (dst, weight) ----------------
__global__ void __launch_bounds__(256) k_fill(const int* __restrict__ edge_raw) {
    const int is64 = g_is64;
    const float gmax = fdec(g_max_enc);
    int stride = gridDim.x * blockDim.x;
    for (int i = blockIdx.x * blockDim.x + threadIdx.x; i < E_EDGES; i += stride) {
        int s = edge_at(edge_raw, is64, i);
        int d = edge_at(edge_raw, is64, (long long)E_EDGES + i);
        float e = g_el[s] + g_er[d];
        e = e > 0.f ? e : ALPHA * e;
        float w = expf(e - gmax);
        int pos = g_rowptr[s] + atomicAdd(&g_cursor[s], 1);
        g_dstl[pos] = d;
        g_wl[pos] = w;
    }
}

// ---------------- aggregate: warp per node, no atomics, fused normalize+elu ----------------
__device__ __forceinline__ void fma4(float4& a, float w, const float4& b) {
    a.x = fmaf(w, b.x, a.x); a.y = fmaf(w, b.y, a.y);
    a.z = fmaf(w, b.z, a.z); a.w = fmaf(w, b.w, a.w);
}
__device__ __forceinline__ float elu1(float v) { return v > 0.f ? v : expm1f(v); }

__global__ void __launch_bounds__(256) k_agg(float* __restrict__ out) {
    int gw   = (blockIdx.x * 256 + threadIdx.x) >> 5;
    int lane = threadIdx.x & 31;
    if (gw >= N_NODES) return;
    int beg = g_rowptr[gw];
    int end = beg + g_deg[gw];
    float4 acc0 = make_float4(0.f, 0.f, 0.f, 0.f);
    float4 acc1 = make_float4(0.f, 0.f, 0.f, 0.f);
    float wsum = 0.f;
    int p = beg;
    for (; p + 4 <= end; p += 4) {
        int d0 = g_dstl[p], d1 = g_dstl[p + 1], d2 = g_dstl[p + 2], d3 = g_dstl[p + 3];
        float w0 = g_wl[p], w1 = g_wl[p + 1], w2 = g_wl[p + 2], w3 = g_wl[p + 3];
        const float4* h0 = (const float4*)(g_h + (size_t)d0 * F_OUTDIM);
        const float4* h1 = (const float4*)(g_h + (size_t)d1 * F_OUTDIM);
        const float4* h2 = (const float4*)(g_h + (size_t)d2 * F_OUTDIM);
        const float4* h3 = (const float4*)(g_h + (size_t)d3 * F_OUTDIM);
        float4 x0 = h0[lane], y0 = h0[lane + 32];
        float4 x1 = h1[lane], y1 = h1[lane + 32];
        float4 x2 = h2[lane], y2 = h2[lane + 32];
        float4 x3 = h3[lane], y3 = h3[lane + 32];
        fma4(acc0, w0, x0); fma4(acc1, w0, y0);
        fma4(acc0, w1, x1); fma4(acc1, w1, y1);
        fma4(acc0, w2, x2); fma4(acc1, w2, y2);
        fma4(acc0, w3, x3); fma4(acc1, w3, y3);
        wsum += w0 + w1 + w2 + w3;
    }
    for (; p < end; p++) {
        int d = g_dstl[p];
        float w = g_wl[p];
        const float4* h = (const float4*)(g_h + (size_t)d * F_OUTDIM);
        fma4(acc0, w, h[lane]); fma4(acc1, w, h[lane + 32]);
        wsum += w;
    }
    float inv = 1.0f / (wsum + EPSV);
    float4 v0, v1;
    v0.x = elu1(acc0.x * inv); v0.y = elu1(acc0.y * inv);
    v0.z = elu1(acc0.z * inv); v0.w = elu1(acc0.w * inv);
    v1.x = elu1(acc1.x * inv); v1.y = elu1(acc1.y * inv);
    v1.z = elu1(acc1.z * inv); v1.w = elu1(acc1.w * inv);
    float4* orow = (float4*)(out + (size_t)gw * F_OUTDIM);
    orow[lane]      = v0;
    orow[lane + 32] = v1;
}

// ---------------- launch ----------------
extern "C" void kernel_launch(void* const* d_in, const int* in_sizes, int n_in,
                              void* d_out, int out_size) {
    const float* x    = (const float*)d_in[0];
    const int*   edge = (const int*)d_in[1];   // int32 or int64, auto-detected
    const float* W    = (const float*)d_in[2];
    const float* a    = (const float*)d_in[3];
    const float* bias = (const float*)d_in[4];
    float* out = (float*)d_out;

    k_init<<<392, 256>>>(edge);

    dim3 ggrid(2, (N_NODES + 127) / 128);
    k_gemm<<<ggrid, 256>>>(x, W, bias);

    k_dots<<<(N_NODES * 32 + 255) / 256, 256>>>(a);

    k_count<<<2048, 256>>>(edge);
    k_scan1<<<SCAN_NB, SCAN_BS>>>();
    k_scan2<<<1, 256>>>();
    k_scan3<<<SCAN_NB, SCAN_BS>>>();

    k_edge_max<<<1024, 256>>>(edge);
    k_fill<<<2048, 256>>>(edge);
    k_agg<<<(N_NODES * 32 + 255) / 256, 256>>>(out);
}

// round 6
// speedup vs baseline: 3.0919x; 1.2251x over previous
#include <cuda_runtime.h>
#include <cuda_fp16.h>
#include <cstdint>

#define N_NODES 100000
#define E_EDGES 3200000
#define F_INDIM 512
#define F_OUTDIM 256
#define ALPHA   0.2f
#define EPSV    9e-15f

#define SCAN_BS 512
#define SCAN_NB 196   // 196*512 = 100352 >= 100000

// ---------------- scratch (static device globals; no allocation) ----------------
__device__ __align__(16) __half g_hh[(size_t)N_NODES * F_OUTDIM];  // 51.2 MB, fp16 h
__device__ float    g_elp[2][N_NODES];   // per-colBlk partial dots
__device__ float    g_erp[2][N_NODES];
__device__ float    g_el[N_NODES];
__device__ float    g_er[N_NODES];
__device__ int      g_deg[N_NODES];
__device__ int      g_cursor[N_NODES];
__device__ int      g_rowptr[N_NODES];
__device__ unsigned g_rmax[N_NODES];     // per-row max (encoded)
__device__ int      g_scan[SCAN_NB * SCAN_BS];
__device__ int      g_bsum[SCAN_NB];
__device__ int      g_boff[SCAN_NB];
__device__ int2     g_pair[E_EDGES];     // CSR (dst, w-bits)
__device__ int      g_is64;

// ---------------- helpers ----------------
__device__ __forceinline__ unsigned fenc(float f) {
    unsigned u = __float_as_uint(f);
    return (u & 0x80000000u) ? ~u : (u | 0x80000000u);
}
__device__ __forceinline__ float fdec(unsigned u) {
    return __uint_as_float((u & 0x80000000u) ? (u & 0x7fffffffu) : ~u);
}
__device__ __forceinline__ int edge_at(const int* __restrict__ e32, int is64, long long idx) {
    return is64 ? e32[2 * idx] : e32[(size_t)idx];
}
__device__ __forceinline__ float totf32(float x) {
    uint32_t r;
    asm("cvt.rna.tf32.f32 %0, %1;" : "=r"(r) : "f"(x));
    return __uint_as_float(r);
}

// ---------------- init ----------------
__global__ void k_init(const int* __restrict__ edge_raw) {
    int i = blockIdx.x * blockDim.x + threadIdx.x;
    int stride = gridDim.x * blockDim.x;
    for (; i < N_NODES; i += stride) {
        g_deg[i] = 0; g_cursor[i] = 0; g_rmax[i] = 0u;
    }
    if (blockIdx.x == 0 && threadIdx.x == 0) {
        int all_zero = 1;
        for (int k = 0; k < 16; k++) all_zero &= (edge_raw[2 * k + 1] == 0);
        g_is64 = all_zero;
    }
}

// ---------------- GEMM: h = x @ W + bias via mma.sync tf32; fused partial dots ----------------
#define KC 32
#define AS_STR 36
#define BS_STR 136

__global__ void __launch_bounds__(256) k_gemm(const float* __restrict__ x,
                                              const float* __restrict__ W,
                                              const float* __restrict__ bias,
                                              const float* __restrict__ avec) {
    __shared__ float As[128 * AS_STR];
    __shared__ float Bs[KC * BS_STR];
    __shared__ float sbias[128], sa1[128], sa2[128];
    __shared__ float sel[128][2], ser[128][2];

    const int tid = threadIdx.x;
    const int wid = tid >> 5, lane = tid & 31;
    const int g = lane >> 2, tg = lane & 3;
    const int warpM = wid >> 1, warpN = wid & 1;
    const int rowBlk = blockIdx.y * 128;
    const int colBlk = blockIdx.x * 128;

    if (tid < 128) {
        sbias[tid] = bias[colBlk + tid];
        sa1[tid]   = avec[colBlk + tid];
        sa2[tid]   = avec[F_OUTDIM + colBlk + tid];
    }

    float acc[2][8][4];
    #pragma unroll
    for (int mt = 0; mt < 2; mt++)
        #pragma unroll
        for (int nt = 0; nt < 8; nt++)
            #pragma unroll
            for (int r = 0; r < 4; r++) acc[mt][nt][r] = 0.0f;

    const int am  = tid >> 1;
    const int ak0 = (tid & 1) * 16;
    const int br  = tid >> 3;
    const int bc0 = (tid & 7) * 16;
    const bool avalid = (rowBlk + am) < N_NODES;
    const float* aptr = x + (size_t)(rowBlk + am) * F_INDIM + ak0;
    const float* bptr = W + (size_t)br * F_OUTDIM + colBlk + bc0;

    float4 ra[4], rb[4];
    #pragma unroll
    for (int j = 0; j < 4; j++) {
        ra[j] = avalid ? ((const float4*)(aptr))[j] : make_float4(0.f, 0.f, 0.f, 0.f);
        rb[j] = ((const float4*)(bptr))[j];
    }
    #pragma unroll
    for (int j = 0; j < 4; j++) {
        float4 t = ra[j];
        t.x = totf32(t.x); t.y = totf32(t.y); t.z = totf32(t.z); t.w = totf32(t.w);
        *(float4*)&As[am * AS_STR + ak0 + j * 4] = t;
        float4 u = rb[j];
        u.x = totf32(u.x); u.y = totf32(u.y); u.z = totf32(u.z); u.w = totf32(u.w);
        *(float4*)&Bs[br * BS_STR + bc0 + j * 4] = u;
    }
    __syncthreads();

    for (int c = 0; c < F_INDIM / KC; c++) {
        if (c < F_INDIM / KC - 1) {
            int kt = (c + 1) * KC;
            #pragma unroll
            for (int j = 0; j < 4; j++) {
                ra[j] = avalid ? ((const float4*)(aptr + kt))[j] : make_float4(0.f, 0.f, 0.f, 0.f);
                rb[j] = ((const float4*)(bptr + (size_t)kt * F_OUTDIM))[j];
            }
        }
        #pragma unroll
        for (int kk = 0; kk < KC; kk += 8) {
            uint32_t af[2][4];
            #pragma unroll
            for (int mt = 0; mt < 2; mt++) {
                int m0 = warpM * 32 + mt * 16;
                af[mt][0] = __float_as_uint(As[(m0 + g) * AS_STR + kk + tg]);
                af[mt][1] = __float_as_uint(As[(m0 + g + 8) * AS_STR + kk + tg]);
                af[mt][2] = __float_as_uint(As[(m0 + g) * AS_STR + kk + tg + 4]);
                af[mt][3] = __float_as_uint(As[(m0 + g + 8) * AS_STR + kk + tg + 4]);
            }
            uint32_t bf[8][2];
            #pragma unroll
            for (int nt = 0; nt < 8; nt++) {
                int n0 = warpN * 64 + nt * 8 + g;
                bf[nt][0] = __float_as_uint(Bs[(kk + tg) * BS_STR + n0]);
                bf[nt][1] = __float_as_uint(Bs[(kk + tg + 4) * BS_STR + n0]);
            }
            #pragma unroll
            for (int mt = 0; mt < 2; mt++)
                #pragma unroll
                for (int nt = 0; nt < 8; nt++) {
                    asm volatile(
                        "mma.sync.aligned.m16n8k8.row.col.f32.tf32.tf32.f32 "
                        "{%0,%1,%2,%3}, {%4,%5,%6,%7}, {%8,%9}, {%0,%1,%2,%3};"
                        : "+f"(acc[mt][nt][0]), "+f"(acc[mt][nt][1]),
                          "+f"(acc[mt][nt][2]), "+f"(acc[mt][nt][3])
                        : "r"(af[mt][0]), "r"(af[mt][1]), "r"(af[mt][2]), "r"(af[mt][3]),
                          "r"(bf[nt][0]), "r"(bf[nt][1]));
                }
        }
        __syncthreads();
        if (c < F_INDIM / KC - 1) {
            #pragma unroll
            for (int j = 0; j < 4; j++) {
                float4 t = ra[j];
                t.x = totf32(t.x); t.y = totf32(t.y); t.z = totf32(t.z); t.w = totf32(t.w);
                *(float4*)&As[am * AS_STR + ak0 + j * 4] = t;
                float4 u = rb[j];
                u.x = totf32(u.x); u.y = totf32(u.y); u.z = totf32(u.z); u.w = totf32(u.w);
                *(float4*)&Bs[br * BS_STR + bc0 + j * 4] = u;
            }
            __syncthreads();
        }
    }

    // epilogue: bias add, fp16 h store, fused partial dots (deterministic)
    #pragma unroll
    for (int mt = 0; mt < 2; mt++) {
        #pragma unroll
        for (int rr = 0; rr < 2; rr++) {
            int rloc = warpM * 32 + mt * 16 + g + rr * 8;
            int grow = rowBlk + rloc;
            bool rvalid = grow < N_NODES;
            __half* hp = g_hh + (size_t)grow * F_OUTDIM + colBlk + warpN * 64;
            float s1 = 0.f, s2 = 0.f;
            #pragma unroll
            for (int nt = 0; nt < 8; nt++) {
                int col = nt * 8 + tg * 2;
                float v0 = acc[mt][nt][rr * 2 + 0] + sbias[warpN * 64 + col];
                float v1 = acc[mt][nt][rr * 2 + 1] + sbias[warpN * 64 + col + 1];
                s1 += v0 * sa1[warpN * 64 + col] + v1 * sa1[warpN * 64 + col + 1];
                s2 += v0 * sa2[warpN * 64 + col] + v1 * sa2[warpN * 64 + col + 1];
                if (rvalid)
                    *(__half2*)(hp + col) = __floats2half2_rn(v0, v1);
            }
            // reduce over tg quad (lanes g*4 + tg)
            s1 += __shfl_xor_sync(0xffffffffu, s1, 1);
            s1 += __shfl_xor_sync(0xffffffffu, s1, 2);
            s2 += __shfl_xor_sync(0xffffffffu, s2, 1);
            s2 += __shfl_xor_sync(0xffffffffu, s2, 2);
            if (tg == 0) { sel[rloc][warpN] = s1; ser[rloc][warpN] = s2; }
        }
    }
    __syncthreads();
    if (tid < 128) {
        int grow = rowBlk + tid;
        if (grow < N_NODES) {
            g_elp[blockIdx.x][grow] = sel[tid][0] + sel[tid][1];
            g_erp[blockIdx.x][grow] = ser[tid][0] + ser[tid][1];
        }
    }
}

// ---------------- combine partial dots ----------------
__global__ void k_prep() {
    int i = blockIdx.x * blockDim.x + threadIdx.x;
    if (i < N_NODES) {
        g_el[i] = g_elp[0][i] + g_elp[1][i];
        g_er[i] = g_erp[0][i] + g_erp[1][i];
    }
}

// ---------------- count degrees + per-row max of leaky-relu'd scores ----------------
__global__ void __launch_bounds__(256) k_count(const int* __restrict__ edge_raw) {
    const int is64 = g_is64;
    int stride = gridDim.x * blockDim.x;
    for (int i = blockIdx.x * blockDim.x + threadIdx.x; i < E_EDGES; i += stride) {
        int s = edge_at(edge_raw, is64, i);
        int d = edge_at(edge_raw, is64, (long long)E_EDGES + i);
        float e = g_el[s] + g_er[d];
        e = e > 0.f ? e : ALPHA * e;
        atomicAdd(&g_deg[s], 1);
        atomicMax(&g_rmax[s], fenc(e));
    }
}

// ---------------- scan (3 passes) ----------------
__global__ void __launch_bounds__(SCAN_BS) k_scan1() {
    __shared__ int sm[SCAN_BS];
    int t = threadIdx.x;
    int i = blockIdx.x * SCAN_BS + t;
    int v = (i < N_NODES) ? g_deg[i] : 0;
    sm[t] = v;
    __syncthreads();
    #pragma unroll
    for (int off = 1; off < SCAN_BS; off <<= 1) {
        int add = (t >= off) ? sm[t - off] : 0;
        __syncthreads();
        sm[t] += add;
        __syncthreads();
    }
    g_scan[i] = sm[t];
    if (t == SCAN_BS - 1) g_bsum[blockIdx.x] = sm[t];
}

__global__ void k_scan2() {
    __shared__ int sm[SCAN_NB];
    int t = threadIdx.x;
    if (t < SCAN_NB) sm[t] = g_bsum[t];
    __syncthreads();
    if (t == 0) {
        int run = 0;
        for (int i = 0; i < SCAN_NB; i++) { int v = sm[i]; sm[i] = run; run += v; }
    }
    __syncthreads();
    if (t < SCAN_NB) g_boff[t] = sm[t];
}

__global__ void __launch_bounds__(SCAN_BS) k_scan3() {
    int i = blockIdx.x * SCAN_BS + threadIdx.x;
    if (i < N_NODES)
        g_rowptr[i] = g_scan[i] - g_deg[i] + g_boff[blockIdx.x];
}

// ---------------- fill CSR (dst, weight) pairs ----------------
__global__ void __launch_bounds__(256) k_fill(const int* __restrict__ edge_raw) {
    const int is64 = g_is64;
    int stride = gridDim.x * blockDim.x;
    for (int i = blockIdx.x * blockDim.x + threadIdx.x; i < E_EDGES; i += stride) {
        int s = edge_at(edge_raw, is64, i);
        int d = edge_at(edge_raw, is64, (long long)E_EDGES + i);
        float e = g_el[s] + g_er[d];
        e = e > 0.f ? e : ALPHA * e;
        float w = expf(e - fdec(g_rmax[s]));
        int pos = g_rowptr[s] + atomicAdd(&g_cursor[s], 1);
        g_pair[pos] = make_int2(d, __float_as_int(w));
    }
}

// ---------------- aggregate: warp per node, fp16 h gather, fused normalize+elu ----------------
__device__ __forceinline__ float elu1(float v) { return v > 0.f ? v : expm1f(v); }

__device__ __forceinline__ void acc8(float* acc, float w, uint4 raw) {
    __half2 h0 = *(__half2*)&raw.x, h1 = *(__half2*)&raw.y;
    __half2 h2 = *(__half2*)&raw.z, h3 = *(__half2*)&raw.w;
    float2 f0 = __half22float2(h0), f1 = __half22float2(h1);
    float2 f2 = __half22float2(h2), f3 = __half22float2(h3);
    acc[0] = fmaf(w, f0.x, acc[0]); acc[1] = fmaf(w, f0.y, acc[1]);
    acc[2] = fmaf(w, f1.x, acc[2]); acc[3] = fmaf(w, f1.y, acc[3]);
    acc[4] = fmaf(w, f2.x, acc[4]); acc[5] = fmaf(w, f2.y, acc[5]);
    acc[6] = fmaf(w, f3.x, acc[6]); acc[7] = fmaf(w, f3.y, acc[7]);
}

__global__ void __launch_bounds__(256) k_agg(float* __restrict__ out) {
    int gw   = (blockIdx.x * 256 + threadIdx.x) >> 5;
    int lane = threadIdx.x & 31;
    if (gw >= N_NODES) return;
    int beg = g_rowptr[gw];
    int end = beg + g_deg[gw];
    float acc[8] = {0.f, 0.f, 0.f, 0.f, 0.f, 0.f, 0.f, 0.f};
    float wsum = 0.f;
    int p = beg;
    for (; p + 2 <= end; p += 2) {
        int2 e0 = g_pair[p], e1 = g_pair[p + 1];
        float w0 = __int_as_float(e0.y), w1 = __int_as_float(e1.y);
        const uint4* h0 = (const uint4*)(g_hh + (size_t)e0.x * F_OUTDIM);
        const uint4* h1 = (const uint4*)(g_hh + (size_t)e1.x * F_OUTDIM);
        uint4 r0 = h0[lane];
        uint4 r1 = h1[lane];
        acc8(acc, w0, r0);
        acc8(acc, w1, r1);
        wsum += w0 + w1;
    }
    if (p < end) {
        int2 e0 = g_pair[p];
        float w0 = __int_as_float(e0.y);
        const uint4* h0 = (const uint4*)(g_hh + (size_t)e0.x * F_OUTDIM);
        acc8(acc, w0, h0[lane]);
        wsum += w0;
    }
    float inv = 1.0f / (wsum + EPSV);
    float4 v0, v1;
    v0.x = elu1(acc[0] * inv); v0.y = elu1(acc[1] * inv);
    v0.z = elu1(acc[2] * inv); v0.w = elu1(acc[3] * inv);
    v1.x = elu1(acc[4] * inv); v1.y = elu1(acc[5] * inv);
    v1.z = elu1(acc[6] * inv); v1.w = elu1(acc[7] * inv);
    float4* orow = (float4*)(out + (size_t)gw * F_OUTDIM + lane * 8);
    orow[0] = v0;
    orow[1] = v1;
}

// ---------------- launch ----------------
extern "C" void kernel_launch(void* const* d_in, const int* in_sizes, int n_in,
                              void* d_out, int out_size) {
    const float* x    = (const float*)d_in[0];
    const int*   edge = (const int*)d_in[1];   // int32 or int64, auto-detected
    const float* W    = (const float*)d_in[2];
    const float* a    = (const float*)d_in[3];
    const float* bias = (const float*)d_in[4];
    float* out = (float*)d_out;

    k_init<<<392, 256>>>(edge);

    dim3 ggrid(2, (N_NODES + 127) / 128);
    k_gemm<<<ggrid, 256>>>(x, W, bias, a);
    k_prep<<<(N_NODES + 255) / 256, 256>>>();

    k_count<<<2048, 256>>>(edge);
    k_scan1<<<SCAN_NB, SCAN_BS>>>();
    k_scan2<<<1, 256>>>();
    k_scan3<<<SCAN_NB, SCAN_BS>>>();
    k_fill<<<2048, 256>>>(edge);
    k_agg<<<(N_NODES * 32 + 255) / 256, 256>>>(out);
}

// round 7
// speedup vs baseline: 4.1466x; 1.3411x over previous
#include <cuda_runtime.h>
#include <cuda_fp16.h>
#include <cstdint>

#define N_NODES 100000
#define E_EDGES 3200000
#define F_INDIM 512
#define F_OUTDIM 256
#define ALPHA   0.2f
#define EPSV    9e-15f

#define SCAN_BS 512
#define SCAN_NB 196   // 196*512 = 100352 >= 100000

// ---------------- scratch (static device globals; no allocation) ----------------
__device__ __align__(16) __half g_hh[(size_t)N_NODES * F_OUTDIM];  // 51.2 MB fp16 h
__device__ __align__(16) __half g_wth[(size_t)F_OUTDIM * F_INDIM]; // W^T fp16 [n][k]
__device__ float    g_elp[2][N_NODES];
__device__ float    g_erp[2][N_NODES];
__device__ float    g_el[N_NODES];
__device__ float    g_er[N_NODES];
__device__ int      g_deg[N_NODES];
__device__ int      g_cursor[N_NODES];
__device__ int      g_rowptr[N_NODES];
__device__ int      g_scan[SCAN_NB * SCAN_BS];
__device__ int      g_bsum[SCAN_NB];
__device__ int      g_boff[SCAN_NB];
__device__ int2     g_pair[E_EDGES];     // CSR (dst, w-bits)
__device__ int      g_is64;

// ---------------- helpers ----------------
__device__ __forceinline__ int edge_at(const int* __restrict__ e32, int is64, long long idx) {
    return is64 ? e32[2 * idx] : e32[(size_t)idx];
}
__device__ __forceinline__ uint32_t packh2(float a, float b) {
    __half2 h = __floats2half2_rn(a, b);
    return *(uint32_t*)&h;
}

// ---------------- init ----------------
__global__ void k_init(const int* __restrict__ edge_raw) {
    int i = blockIdx.x * blockDim.x + threadIdx.x;
    int stride = gridDim.x * blockDim.x;
    for (; i < N_NODES; i += stride) { g_deg[i] = 0; g_cursor[i] = 0; }
    if (blockIdx.x == 0 && threadIdx.x == 0) {
        int all_zero = 1;
        for (int k = 0; k < 16; k++) all_zero &= (edge_raw[2 * k + 1] == 0);
        g_is64 = all_zero;
    }
}

// ---------------- W^T fp16: g_wth[n][k] ----------------
__global__ void k_wt(const float* __restrict__ W) {
    int kp = blockIdx.x;       // 0..255 (k pair)
    int n  = threadIdx.x;      // 0..255
    float w0 = W[(size_t)(2 * kp) * F_OUTDIM + n];
    float w1 = W[(size_t)(2 * kp + 1) * F_OUTDIM + n];
    ((uint32_t*)g_wth)[n * (F_INDIM / 2) + kp] = packh2(w0, w1);
}

// ---------------- GEMM: h = x @ W + bias via mma.sync m16n8k16 fp16; fused dots ----------------
#define KC 32
#define AS_W 20   // half2 words per A row (16 data + 4 pad; 20 mod 32 == 4*odd -> bijective banks)
#define BS_W 20

__global__ void __launch_bounds__(256) k_gemm(const float* __restrict__ x,
                                              const float* __restrict__ bias,
                                              const float* __restrict__ avec) {
    __shared__ uint32_t As[128 * AS_W];   // [m][k/2] half2
    __shared__ uint32_t Bs[128 * BS_W];   // [n][k/2] half2 (W^T)
    __shared__ float sbias[128], sa1[128], sa2[128];
    __shared__ float sel[128][2], ser[128][2];

    const int tid = threadIdx.x;
    const int wid = tid >> 5, lane = tid & 31;
    const int g = lane >> 2, tg = lane & 3;
    const int warpM = wid >> 1, warpN = wid & 1;
    const int rowBlk = blockIdx.y * 128;
    const int colBlk = blockIdx.x * 128;

    if (tid < 128) {
        sbias[tid] = bias[colBlk + tid];
        sa1[tid]   = avec[colBlk + tid];
        sa2[tid]   = avec[F_OUTDIM + colBlk + tid];
    }

    float acc[2][8][4];
    #pragma unroll
    for (int mt = 0; mt < 2; mt++)
        #pragma unroll
        for (int nt = 0; nt < 8; nt++)
            #pragma unroll
            for (int r = 0; r < 4; r++) acc[mt][nt][r] = 0.0f;

    // staging addressing
    const int am  = tid >> 1;              // 0..127
    const int ak0 = (tid & 1) * 16;        // float offset 0/16
    const int ah0 = (tid & 1) * 8;         // half2-word offset 0/8
    const bool avalid = (rowBlk + am) < N_NODES;
    const float* aptr = x + (size_t)(rowBlk + am) * F_INDIM + ak0;
    // B: same thread mapping on n
    const uint32_t* wtp = (const uint32_t*)g_wth + (size_t)(colBlk + am) * (F_INDIM / 2) + ah0;

    float4 ra[4];
    uint4  rb[2];

    // load chunk 0
    #pragma unroll
    for (int j = 0; j < 4; j++)
        ra[j] = avalid ? ((const float4*)aptr)[j] : make_float4(0.f, 0.f, 0.f, 0.f);
    rb[0] = ((const uint4*)wtp)[0];
    rb[1] = ((const uint4*)wtp)[1];

    #pragma unroll
    for (int j = 0; j < 2; j++) {
        uint4 w;
        w.x = packh2(ra[2*j].x, ra[2*j].y);  w.y = packh2(ra[2*j].z, ra[2*j].w);
        w.z = packh2(ra[2*j+1].x, ra[2*j+1].y); w.w = packh2(ra[2*j+1].z, ra[2*j+1].w);
        *(uint4*)&As[am * AS_W + ah0 + j * 4] = w;
        *(uint4*)&Bs[am * BS_W + ah0 + j * 4] = rb[j];
    }
    __syncthreads();

    for (int c = 0; c < F_INDIM / KC; c++) {
        if (c < F_INDIM / KC - 1) {
            int kt = (c + 1) * KC;
            #pragma unroll
            for (int j = 0; j < 4; j++)
                ra[j] = avalid ? ((const float4*)(aptr + kt))[j] : make_float4(0.f, 0.f, 0.f, 0.f);
            rb[0] = ((const uint4*)(wtp + (kt >> 1)))[0];
            rb[1] = ((const uint4*)(wtp + (kt >> 1)))[1];
        }
        #pragma unroll
        for (int kk = 0; kk < KC / 2; kk += 8) {    // half2-word offset: 0, 8
            uint32_t af[2][4];
            #pragma unroll
            for (int mt = 0; mt < 2; mt++) {
                int m0 = warpM * 32 + mt * 16;
                af[mt][0] = As[(m0 + g) * AS_W + kk + tg];
                af[mt][1] = As[(m0 + g + 8) * AS_W + kk + tg];
                af[mt][2] = As[(m0 + g) * AS_W + kk + tg + 4];
                af[mt][3] = As[(m0 + g + 8) * AS_W + kk + tg + 4];
            }
            uint32_t bf[8][2];
            #pragma unroll
            for (int nt = 0; nt < 8; nt++) {
                int n0 = warpN * 64 + nt * 8 + g;
                bf[nt][0] = Bs[n0 * BS_W + kk + tg];
                bf[nt][1] = Bs[n0 * BS_W + kk + tg + 4];
            }
            #pragma unroll
            for (int mt = 0; mt < 2; mt++)
                #pragma unroll
                for (int nt = 0; nt < 8; nt++) {
                    asm volatile(
                        "mma.sync.aligned.m16n8k16.row.col.f32.f16.f16.f32 "
                        "{%0,%1,%2,%3}, {%4,%5,%6,%7}, {%8,%9}, {%0,%1,%2,%3};"
                        : "+f"(acc[mt][nt][0]), "+f"(acc[mt][nt][1]),
                          "+f"(acc[mt][nt][2]), "+f"(acc[mt][nt][3])
                        : "r"(af[mt][0]), "r"(af[mt][1]), "r"(af[mt][2]), "r"(af[mt][3]),
                          "r"(bf[nt][0]), "r"(bf[nt][1]));
                }
        }
        __syncthreads();
        if (c < F_INDIM / KC - 1) {
            #pragma unroll
            for (int j = 0; j < 2; j++) {
                uint4 w;
                w.x = packh2(ra[2*j].x, ra[2*j].y);  w.y = packh2(ra[2*j].z, ra[2*j].w);
                w.z = packh2(ra[2*j+1].x, ra[2*j+1].y); w.w = packh2(ra[2*j+1].z, ra[2*j+1].w);
                *(uint4*)&As[am * AS_W + ah0 + j * 4] = w;
                *(uint4*)&Bs[am * BS_W + ah0 + j * 4] = rb[j];
            }
            __syncthreads();
        }
    }

    // epilogue: bias add, fp16 h store, fused partial dots (deterministic)
    #pragma unroll
    for (int mt = 0; mt < 2; mt++) {
        #pragma unroll
        for (int rr = 0; rr < 2; rr++) {
            int rloc = warpM * 32 + mt * 16 + g + rr * 8;
            int grow = rowBlk + rloc;
            bool rvalid = grow < N_NODES;
            __half* hp = g_hh + (size_t)grow * F_OUTDIM + colBlk + warpN * 64;
            float s1 = 0.f, s2 = 0.f;
            #pragma unroll
            for (int nt = 0; nt < 8; nt++) {
                int col = nt * 8 + tg * 2;
                float v0 = acc[mt][nt][rr * 2 + 0] + sbias[warpN * 64 + col];
                float v1 = acc[mt][nt][rr * 2 + 1] + sbias[warpN * 64 + col + 1];
                s1 += v0 * sa1[warpN * 64 + col] + v1 * sa1[warpN * 64 + col + 1];
                s2 += v0 * sa2[warpN * 64 + col] + v1 * sa2[warpN * 64 + col + 1];
                if (rvalid)
                    *(__half2*)(hp + col) = __floats2half2_rn(v0, v1);
            }
            s1 += __shfl_xor_sync(0xffffffffu, s1, 1);
            s1 += __shfl_xor_sync(0xffffffffu, s1, 2);
            s2 += __shfl_xor_sync(0xffffffffu, s2, 1);
            s2 += __shfl_xor_sync(0xffffffffu, s2, 2);
            if (tg == 0) { sel[rloc][warpN] = s1; ser[rloc][warpN] = s2; }
        }
    }
    __syncthreads();
    if (tid < 128) {
        int grow = rowBlk + tid;
        if (grow < N_NODES) {
            g_elp[blockIdx.x][grow] = sel[tid][0] + sel[tid][1];
            g_erp[blockIdx.x][grow] = ser[tid][0] + ser[tid][1];
        }
    }
}

// ---------------- combine partial dots ----------------
__global__ void k_prep() {
    int i = blockIdx.x * blockDim.x + threadIdx.x;
    if (i < N_NODES) {
        g_el[i] = g_elp[0][i] + g_elp[1][i];
        g_er[i] = g_erp[0][i] + g_erp[1][i];
    }
}

// ---------------- count degrees (src only) ----------------
__global__ void __launch_bounds__(256) k_count(const int* __restrict__ edge_raw) {
    const int is64 = g_is64;
    int stride = gridDim.x * blockDim.x;
    for (int i = blockIdx.x * blockDim.x + threadIdx.x; i < E_EDGES; i += stride) {
        int s = edge_at(edge_raw, is64, i);
        atomicAdd(&g_deg[s], 1);
    }
}

// ---------------- scan (3 passes) ----------------
__global__ void __launch_bounds__(SCAN_BS) k_scan1() {
    __shared__ int sm[SCAN_BS];
    int t = threadIdx.x;
    int i = blockIdx.x * SCAN_BS + t;
    int v = (i < N_NODES) ? g_deg[i] : 0;
    sm[t] = v;
    __syncthreads();
    #pragma unroll
    for (int off = 1; off < SCAN_BS; off <<= 1) {
        int add = (t >= off) ? sm[t - off] : 0;
        __syncthreads();
        sm[t] += add;
        __syncthreads();
    }
    g_scan[i] = sm[t];
    if (t == SCAN_BS - 1) g_bsum[blockIdx.x] = sm[t];
}

__global__ void k_scan2() {
    __shared__ int sm[SCAN_NB];
    int t = threadIdx.x;
    if (t < SCAN_NB) sm[t] = g_bsum[t];
    __syncthreads();
    if (t == 0) {
        int run = 0;
        for (int i = 0; i < SCAN_NB; i++) { int v = sm[i]; sm[i] = run; run += v; }
    }
    __syncthreads();
    if (t < SCAN_NB) g_boff[t] = sm[t];
}

__global__ void __launch_bounds__(SCAN_BS) k_scan3() {
    int i = blockIdx.x * SCAN_BS + threadIdx.x;
    if (i < N_NODES)
        g_rowptr[i] = g_scan[i] - g_deg[i] + g_boff[blockIdx.x];
}

// ---------------- fill CSR: w = exp(leaky(e)) directly (max shift cancels) ----------------
__global__ void __launch_bounds__(256) k_fill(const int* __restrict__ edge_raw) {
    const int is64 = g_is64;
    int stride = gridDim.x * blockDim.x;
    for (int i = blockIdx.x * blockDim.x + threadIdx.x; i < E_EDGES; i += stride) {
        int s = edge_at(edge_raw, is64, i);
        int d = edge_at(edge_raw, is64, (long long)E_EDGES + i);
        float e = g_el[s] + g_er[d];
        e = e > 0.f ? e : ALPHA * e;
        float w = expf(e);
        int pos = g_rowptr[s] + atomicAdd(&g_cursor[s], 1);
        g_pair[pos] = make_int2(d, __float_as_int(w));
    }
}

// ---------------- aggregate: warp per node, fp16 gather, fused normalize+elu ----------------
__device__ __forceinline__ float elu1(float v) { return v > 0.f ? v : expm1f(v); }

__device__ __forceinline__ void acc8(float* acc, float w, uint4 raw) {
    __half2 h0 = *(__half2*)&raw.x, h1 = *(__half2*)&raw.y;
    __half2 h2 = *(__half2*)&raw.z, h3 = *(__half2*)&raw.w;
    float2 f0 = __half22float2(h0), f1 = __half22float2(h1);
    float2 f2 = __half22float2(h2), f3 = __half22float2(h3);
    acc[0] = fmaf(w, f0.x, acc[0]); acc[1] = fmaf(w, f0.y, acc[1]);
    acc[2] = fmaf(w, f1.x, acc[2]); acc[3] = fmaf(w, f1.y, acc[3]);
    acc[4] = fmaf(w, f2.x, acc[4]); acc[5] = fmaf(w, f2.y, acc[5]);
    acc[6] = fmaf(w, f3.x, acc[6]); acc[7] = fmaf(w, f3.y, acc[7]);
}

__global__ void __launch_bounds__(256) k_agg(float* __restrict__ out) {
    int gw   = (blockIdx.x * 256 + threadIdx.x) >> 5;
    int lane = threadIdx.x & 31;
    if (gw >= N_NODES) return;
    int beg = g_rowptr[gw];
    int end = beg + g_deg[gw];
    float acc[8] = {0.f, 0.f, 0.f, 0.f, 0.f, 0.f, 0.f, 0.f};
    float wsum = 0.f;
    int p = beg;
    for (; p + 2 <= end; p += 2) {
        int2 e0 = g_pair[p], e1 = g_pair[p + 1];
        float w0 = __int_as_float(e0.y), w1 = __int_as_float(e1.y);
        const uint4* h0 = (const uint4*)(g_hh + (size_t)e0.x * F_OUTDIM);
        const uint4* h1 = (const uint4*)(g_hh + (size_t)e1.x * F_OUTDIM);
        uint4 r0 = h0[lane];
        uint4 r1 = h1[lane];
        acc8(acc, w0, r0);
        acc8(acc, w1, r1);
        wsum += w0 + w1;
    }
    if (p < end) {
        int2 e0 = g_pair[p];
        float w0 = __int_as_float(e0.y);
        const uint4* h0 = (const uint4*)(g_hh + (size_t)e0.x * F_OUTDIM);
        acc8(acc, w0, h0[lane]);
        wsum += w0;
    }
    float inv = 1.0f / (wsum + EPSV);
    float4 v0, v1;
    v0.x = elu1(acc[0] * inv); v0.y = elu1(acc[1] * inv);
    v0.z = elu1(acc[2] * inv); v0.w = elu1(acc[3] * inv);
    v1.x = elu1(acc[4] * inv); v1.y = elu1(acc[5] * inv);
    v1.z = elu1(acc[6] * inv); v1.w = elu1(acc[7] * inv);
    float4* orow = (float4*)(out + (size_t)gw * F_OUTDIM + lane * 8);
    orow[0] = v0;
    orow[1] = v1;
}

// ---------------- launch ----------------
extern "C" void kernel_launch(void* const* d_in, const int* in_sizes, int n_in,
                              void* d_out, int out_size) {
    const float* x    = (const float*)d_in[0];
    const int*   edge = (const int*)d_in[1];   // int32 or int64, auto-detected
    const float* W    = (const float*)d_in[2];
    const float* a    = (const float*)d_in[3];
    const float* bias = (const float*)d_in[4];
    float* out = (float*)d_out;

    k_init<<<392, 256>>>(edge);
    k_wt<<<F_INDIM / 2, F_OUTDIM>>>(W);

    dim3 ggrid(2, (N_NODES + 127) / 128);
    k_gemm<<<ggrid, 256>>>(x, bias, a);
    k_prep<<<(N_NODES + 255) / 256, 256>>>();

    k_count<<<2048, 256>>>(edge);
    k_scan1<<<SCAN_NB, SCAN_BS>>>();
    k_scan2<<<1, 256>>>();
    k_scan3<<<SCAN_NB, SCAN_BS>>>();
    k_fill<<<2048, 256>>>(edge);
    k_agg<<<(N_NODES * 32 + 255) / 256, 256>>>(out);
}